// round 1
// baseline (speedup 1.0000x reference)
#include <cuda_runtime.h>
#include <cstdint>

// ---------------------------------------------------------------------------
// MetaNet: hidden = relu(x @ W_hidden^T + b_hidden); out_i = h_i @ W_heads[i]^T + b_heads[i]
// x:        [1024, 1920] f32
// W_hidden: [1792, 1920] f32   (1792 = 14*128)
// b_hidden: [1792]
// W_heads:  [14, 36928, 128] f32
// b_heads:  [14, 36928]
// out: concat of (1024, p_i) row-major blocks, p = SIZES below, total 1024*360320 f32
// ---------------------------------------------------------------------------

namespace {

constexpr int NUM_HEADS = 14;
constexpr int BROWS  = 1024;
constexpr int DIN    = 1920;
constexpr int DSLICE = 128;
constexpr int HID    = NUM_HEADS * DSLICE;   // 1792
constexpr int PMAX   = 36928;

constexpr int BM = 128, BN = 128, BK = 32;
constexpr int SST = BK + 4;                  // smem row stride (36 floats)

// Per-head output widths
__constant__ int c_p[NUM_HEADS] =
    {9280,18496,36928,36928,36928,36928,36928,36928,36928,18496,9280,18496,18496,9280};
// First global N-tile index of each head (tiles of 128 cols; ceil(p/128) per head)
__constant__ int c_tile_start[NUM_HEADS] =
    {0,73,218,507,796,1085,1374,1663,1952,2241,2386,2459,2604,2749};
// Cumulative column offset (elements per row) of each head's output block
__constant__ int c_cum[NUM_HEADS] =
    {0,9280,27776,64704,101632,138560,175488,212416,249344,286272,304768,314048,332544,351040};

constexpr int TOTAL_NTILES = 2822;           // sum of ceil(p_i/128)
constexpr int MTILES = BROWS / BM;           // 8

// Intermediate hidden activations (static device scratch; no allocation allowed)
__device__ float g_hidden[(size_t)BROWS * HID];

__device__ __forceinline__ uint32_t f2tf32(float f) {
    uint32_t r;
    asm("cvt.rna.tf32.f32 %0, %1;" : "=r"(r) : "f"(f));
    return r;
}

__device__ __forceinline__ void mma_tf32(float* c, const uint32_t* a, const uint32_t* b) {
    asm volatile(
        "mma.sync.aligned.m16n8k8.row.col.f32.tf32.tf32.f32 "
        "{%0,%1,%2,%3}, {%4,%5,%6,%7}, {%8,%9}, {%0,%1,%2,%3};\n"
        : "+f"(c[0]), "+f"(c[1]), "+f"(c[2]), "+f"(c[3])
        : "r"(a[0]), "r"(a[1]), "r"(a[2]), "r"(a[3]),
          "r"(b[0]), "r"(b[1]));
}

// ---------------------------------------------------------------------------
// Kernel A: hidden = relu(x @ W_hidden^T + b_hidden)   M=1024, N=1792, K=1920
// grid = 8 (m) * 14 (n) = 112 CTAs, 256 threads
// ---------------------------------------------------------------------------
__global__ void __launch_bounds__(256)
hidden_gemm(const float* __restrict__ x,
            const float* __restrict__ Wh,
            const float* __restrict__ bh)
{
    __shared__ float As[BM][SST];
    __shared__ float Bs[BN][SST];

    const int mtile = blockIdx.x & 7;
    const int ntile = blockIdx.x >> 3;
    const int m0 = mtile * BM;
    const int n0 = ntile * BN;

    const int tid  = threadIdx.x;
    const int lane = tid & 31;
    const int warp = tid >> 5;
    const int wm = warp >> 1;   // 0..3, 32 rows each
    const int wn = warp & 1;    // 0..1, 64 cols each

    float acc[2][8][4];
    #pragma unroll
    for (int t = 0; t < 2; ++t)
        #pragma unroll
        for (int j = 0; j < 8; ++j)
            #pragma unroll
            for (int q = 0; q < 4; ++q) acc[t][j][q] = 0.f;

    for (int k0 = 0; k0 < DIN; k0 += BK) {
        #pragma unroll
        for (int it = 0; it < 4; ++it) {
            int slot = tid + it * 256;           // 0..1023
            int r  = slot >> 3;
            int c4 = (slot & 7) * 4;
            float4 va = *reinterpret_cast<const float4*>(
                x + (size_t)(m0 + r) * DIN + k0 + c4);
            As[r][c4 + 0] = __uint_as_float(f2tf32(va.x));
            As[r][c4 + 1] = __uint_as_float(f2tf32(va.y));
            As[r][c4 + 2] = __uint_as_float(f2tf32(va.z));
            As[r][c4 + 3] = __uint_as_float(f2tf32(va.w));
            float4 vb = *reinterpret_cast<const float4*>(
                Wh + (size_t)(n0 + r) * DIN + k0 + c4);
            Bs[r][c4 + 0] = __uint_as_float(f2tf32(vb.x));
            Bs[r][c4 + 1] = __uint_as_float(f2tf32(vb.y));
            Bs[r][c4 + 2] = __uint_as_float(f2tf32(vb.z));
            Bs[r][c4 + 3] = __uint_as_float(f2tf32(vb.w));
        }
        __syncthreads();

        #pragma unroll
        for (int ks = 0; ks < BK; ks += 8) {
            uint32_t a[2][4];
            #pragma unroll
            for (int t = 0; t < 2; ++t) {
                int row = wm * 32 + t * 16 + (lane >> 2);
                int kc  = ks + (lane & 3);
                a[t][0] = __float_as_uint(As[row][kc]);
                a[t][1] = __float_as_uint(As[row + 8][kc]);
                a[t][2] = __float_as_uint(As[row][kc + 4]);
                a[t][3] = __float_as_uint(As[row + 8][kc + 4]);
            }
            #pragma unroll
            for (int j = 0; j < 8; ++j) {
                int col = wn * 64 + j * 8 + (lane >> 2);
                int kc  = ks + (lane & 3);
                uint32_t b[2];
                b[0] = __float_as_uint(Bs[col][kc]);
                b[1] = __float_as_uint(Bs[col][kc + 4]);
                mma_tf32(acc[0][j], a[0], b);
                mma_tf32(acc[1][j], a[1], b);
            }
        }
        __syncthreads();
    }

    // Epilogue: bias + relu, float2 coalesced stores
    #pragma unroll
    for (int t = 0; t < 2; ++t) {
        int row = m0 + wm * 32 + t * 16 + (lane >> 2);
        #pragma unroll
        for (int j = 0; j < 8; ++j) {
            int col = n0 + wn * 64 + j * 8 + 2 * (lane & 3);
            float b0 = bh[col], b1 = bh[col + 1];
            float2 v0 = make_float2(fmaxf(acc[t][j][0] + b0, 0.f),
                                    fmaxf(acc[t][j][1] + b1, 0.f));
            float2 v1 = make_float2(fmaxf(acc[t][j][2] + b0, 0.f),
                                    fmaxf(acc[t][j][3] + b1, 0.f));
            *reinterpret_cast<float2*>(&g_hidden[(size_t)row * HID + col])       = v0;
            *reinterpret_cast<float2*>(&g_hidden[(size_t)(row + 8) * HID + col]) = v1;
        }
    }
}

// ---------------------------------------------------------------------------
// Kernel B: out_i = h_i @ W_heads[i]^T + b_heads[i]    M=1024, N=p_i, K=128
// grid = TOTAL_NTILES * 8 CTAs, 256 threads
// ---------------------------------------------------------------------------
__global__ void __launch_bounds__(256)
head_gemm(const float* __restrict__ Wheads,
          const float* __restrict__ bheads,
          float* __restrict__ out)
{
    __shared__ float As[BM][SST];
    __shared__ float Bs[BN][SST];

    const int mtile = blockIdx.x & 7;
    const int ntg   = blockIdx.x >> 3;

    int h = 0;
    #pragma unroll
    for (int i = 1; i < NUM_HEADS; ++i) h += (ntg >= c_tile_start[i]);
    const int ntile = ntg - c_tile_start[h];
    const int p  = c_p[h];
    const int n0 = ntile * BN;
    const int m0 = mtile * BM;

    const float* Ag = g_hidden + (size_t)m0 * HID + (size_t)h * DSLICE;  // row stride HID
    const float* Bg = Wheads + (size_t)h * PMAX * DSLICE;                 // row stride 128
    const float* bias = bheads + (size_t)h * PMAX;
    float* Og = out + (size_t)c_cum[h] * BROWS;                           // [1024, p] block

    const int tid  = threadIdx.x;
    const int lane = tid & 31;
    const int warp = tid >> 5;
    const int wm = warp >> 1;
    const int wn = warp & 1;

    float acc[2][8][4];
    #pragma unroll
    for (int t = 0; t < 2; ++t)
        #pragma unroll
        for (int j = 0; j < 8; ++j)
            #pragma unroll
            for (int q = 0; q < 4; ++q) acc[t][j][q] = 0.f;

    #pragma unroll
    for (int k0 = 0; k0 < DSLICE; k0 += BK) {   // 4 iterations
        #pragma unroll
        for (int it = 0; it < 4; ++it) {
            int slot = tid + it * 256;
            int r  = slot >> 3;
            int c4 = (slot & 7) * 4;
            float4 va = *reinterpret_cast<const float4*>(
                Ag + (size_t)r * HID + k0 + c4);
            As[r][c4 + 0] = __uint_as_float(f2tf32(va.x));
            As[r][c4 + 1] = __uint_as_float(f2tf32(va.y));
            As[r][c4 + 2] = __uint_as_float(f2tf32(va.z));
            As[r][c4 + 3] = __uint_as_float(f2tf32(va.w));
            float4 vb;
            if (n0 + r < p) {
                vb = *reinterpret_cast<const float4*>(
                    Bg + (size_t)(n0 + r) * DSLICE + k0 + c4);
            } else {
                vb = make_float4(0.f, 0.f, 0.f, 0.f);
            }
            Bs[r][c4 + 0] = __uint_as_float(f2tf32(vb.x));
            Bs[r][c4 + 1] = __uint_as_float(f2tf32(vb.y));
            Bs[r][c4 + 2] = __uint_as_float(f2tf32(vb.z));
            Bs[r][c4 + 3] = __uint_as_float(f2tf32(vb.w));
        }
        __syncthreads();

        #pragma unroll
        for (int ks = 0; ks < BK; ks += 8) {
            uint32_t a[2][4];
            #pragma unroll
            for (int t = 0; t < 2; ++t) {
                int row = wm * 32 + t * 16 + (lane >> 2);
                int kc  = ks + (lane & 3);
                a[t][0] = __float_as_uint(As[row][kc]);
                a[t][1] = __float_as_uint(As[row + 8][kc]);
                a[t][2] = __float_as_uint(As[row][kc + 4]);
                a[t][3] = __float_as_uint(As[row + 8][kc + 4]);
            }
            #pragma unroll
            for (int j = 0; j < 8; ++j) {
                int col = wn * 64 + j * 8 + (lane >> 2);
                int kc  = ks + (lane & 3);
                uint32_t b[2];
                b[0] = __float_as_uint(Bs[col][kc]);
                b[1] = __float_as_uint(Bs[col][kc + 4]);
                mma_tf32(acc[0][j], a[0], b);
                mma_tf32(acc[1][j], a[1], b);
            }
        }
        __syncthreads();
    }

    // Epilogue: bias add, guarded float2 stores (all p are multiples of 64, cols even)
    #pragma unroll
    for (int t = 0; t < 2; ++t) {
        int row = m0 + wm * 32 + t * 16 + (lane >> 2);
        #pragma unroll
        for (int j = 0; j < 8; ++j) {
            int col = n0 + wn * 64 + j * 8 + 2 * (lane & 3);
            if (col < p) {
                float b0 = bias[col], b1 = bias[col + 1];
                float2 v0 = make_float2(acc[t][j][0] + b0, acc[t][j][1] + b1);
                float2 v1 = make_float2(acc[t][j][2] + b0, acc[t][j][3] + b1);
                *reinterpret_cast<float2*>(&Og[(size_t)row * p + col])       = v0;
                *reinterpret_cast<float2*>(&Og[(size_t)(row + 8) * p + col]) = v1;
            }
        }
    }
}

} // anonymous namespace

extern "C" void kernel_launch(void* const* d_in, const int* in_sizes, int n_in,
                              void* d_out, int out_size) {
    (void)in_sizes; (void)n_in; (void)out_size;
    const float* x      = (const float*)d_in[0];
    const float* Wh     = (const float*)d_in[1];
    const float* bh     = (const float*)d_in[2];
    const float* Wheads = (const float*)d_in[3];
    const float* bheads = (const float*)d_in[4];
    float* out = (float*)d_out;

    hidden_gemm<<<MTILES * (HID / BN), 256>>>(x, Wh, bh);
    head_gemm<<<TOTAL_NTILES * MTILES, 256>>>(Wheads, bheads, out);
}

// round 2
// speedup vs baseline: 1.7893x; 1.7893x over previous
#include <cuda_runtime.h>
#include <cstdint>

// ---------------------------------------------------------------------------
// MetaNet: hidden = relu(x @ W_hidden^T + b_hidden); out_i = h_i @ W_heads[i]^T + b_heads[i]
// ---------------------------------------------------------------------------

namespace {

constexpr int NUM_HEADS = 14;
constexpr int BROWS  = 1024;
constexpr int DIN    = 1920;
constexpr int DSLICE = 128;
constexpr int HID    = NUM_HEADS * DSLICE;   // 1792
constexpr int PMAX   = 36928;

constexpr int BM = 128, BN = 128, BK = 32;
constexpr int SST  = BK + 4;                 // hidden-gemm smem row stride
constexpr int SSTK = DSLICE + 4;             // head-gemm smem row stride (132)
constexpr int ATILE = BM * SSTK;             // floats per A buffer

__constant__ int c_p[NUM_HEADS] =
    {9280,18496,36928,36928,36928,36928,36928,36928,36928,18496,9280,18496,18496,9280};
__constant__ int c_tile_start[NUM_HEADS] =
    {0,73,218,507,796,1085,1374,1663,1952,2241,2386,2459,2604,2749};
__constant__ int c_cum[NUM_HEADS] =
    {0,9280,27776,64704,101632,138560,175488,212416,249344,286272,304768,314048,332544,351040};

constexpr int TOTAL_NTILES = 2822;
constexpr int MTILES = BROWS / BM;           // 8

// smem: B[128][132] + A double-buffer 2*[128][132]
constexpr size_t HEAD_SMEM_BYTES = (size_t)(3 * ATILE) * sizeof(float);  // 202752

// Intermediate hidden activations (tf32-rounded fp32 bits)
__device__ float g_hidden[(size_t)BROWS * HID];

__device__ __forceinline__ uint32_t f2tf32(float f) {
    uint32_t r;
    asm("cvt.rna.tf32.f32 %0, %1;" : "=r"(r) : "f"(f));
    return r;
}

__device__ __forceinline__ void mma_tf32(float* c, const uint32_t* a, const uint32_t* b) {
    asm volatile(
        "mma.sync.aligned.m16n8k8.row.col.f32.tf32.tf32.f32 "
        "{%0,%1,%2,%3}, {%4,%5,%6,%7}, {%8,%9}, {%0,%1,%2,%3};\n"
        : "+f"(c[0]), "+f"(c[1]), "+f"(c[2]), "+f"(c[3])
        : "r"(a[0]), "r"(a[1]), "r"(a[2]), "r"(a[3]),
          "r"(b[0]), "r"(b[1]));
}

__device__ __forceinline__ void cp_async16(float* dst_smem, const float* src) {
    uint32_t d = (uint32_t)__cvta_generic_to_shared(dst_smem);
    asm volatile("cp.async.cg.shared.global [%0], [%1], 16;\n" :: "r"(d), "l"(src));
}

// ---------------------------------------------------------------------------
// Kernel A: hidden = relu(x @ W_hidden^T + b_hidden), stored tf32-rounded
// ---------------------------------------------------------------------------
__global__ void __launch_bounds__(256)
hidden_gemm(const float* __restrict__ x,
            const float* __restrict__ Wh,
            const float* __restrict__ bh)
{
    __shared__ float As[BM][SST];
    __shared__ float Bs[BN][SST];

    const int mtile = blockIdx.x & 7;
    const int ntile = blockIdx.x >> 3;
    const int m0 = mtile * BM;
    const int n0 = ntile * BN;

    const int tid  = threadIdx.x;
    const int lane = tid & 31;
    const int warp = tid >> 5;
    const int wm = warp >> 1;
    const int wn = warp & 1;

    float acc[2][8][4];
    #pragma unroll
    for (int t = 0; t < 2; ++t)
        #pragma unroll
        for (int j = 0; j < 8; ++j)
            #pragma unroll
            for (int q = 0; q < 4; ++q) acc[t][j][q] = 0.f;

    for (int k0 = 0; k0 < DIN; k0 += BK) {
        #pragma unroll
        for (int it = 0; it < 4; ++it) {
            int slot = tid + it * 256;
            int r  = slot >> 3;
            int c4 = (slot & 7) * 4;
            float4 va = *reinterpret_cast<const float4*>(
                x + (size_t)(m0 + r) * DIN + k0 + c4);
            As[r][c4 + 0] = __uint_as_float(f2tf32(va.x));
            As[r][c4 + 1] = __uint_as_float(f2tf32(va.y));
            As[r][c4 + 2] = __uint_as_float(f2tf32(va.z));
            As[r][c4 + 3] = __uint_as_float(f2tf32(va.w));
            float4 vb = *reinterpret_cast<const float4*>(
                Wh + (size_t)(n0 + r) * DIN + k0 + c4);
            Bs[r][c4 + 0] = __uint_as_float(f2tf32(vb.x));
            Bs[r][c4 + 1] = __uint_as_float(f2tf32(vb.y));
            Bs[r][c4 + 2] = __uint_as_float(f2tf32(vb.z));
            Bs[r][c4 + 3] = __uint_as_float(f2tf32(vb.w));
        }
        __syncthreads();

        #pragma unroll
        for (int ks = 0; ks < BK; ks += 8) {
            uint32_t a[2][4];
            #pragma unroll
            for (int t = 0; t < 2; ++t) {
                int row = wm * 32 + t * 16 + (lane >> 2);
                int kc  = ks + (lane & 3);
                a[t][0] = __float_as_uint(As[row][kc]);
                a[t][1] = __float_as_uint(As[row + 8][kc]);
                a[t][2] = __float_as_uint(As[row][kc + 4]);
                a[t][3] = __float_as_uint(As[row + 8][kc + 4]);
            }
            #pragma unroll
            for (int j = 0; j < 8; ++j) {
                int col = wn * 64 + j * 8 + (lane >> 2);
                int kc  = ks + (lane & 3);
                uint32_t b[2];
                b[0] = __float_as_uint(Bs[col][kc]);
                b[1] = __float_as_uint(Bs[col][kc + 4]);
                mma_tf32(acc[0][j], a[0], b);
                mma_tf32(acc[1][j], a[1], b);
            }
        }
        __syncthreads();
    }

    // Epilogue: bias + relu, rounded to tf32 so head kernel can cp.async directly
    #pragma unroll
    for (int t = 0; t < 2; ++t) {
        int row = m0 + wm * 32 + t * 16 + (lane >> 2);
        #pragma unroll
        for (int j = 0; j < 8; ++j) {
            int col = n0 + wn * 64 + j * 8 + 2 * (lane & 3);
            float b0 = bh[col], b1 = bh[col + 1];
            float2 v0, v1;
            v0.x = __uint_as_float(f2tf32(fmaxf(acc[t][j][0] + b0, 0.f)));
            v0.y = __uint_as_float(f2tf32(fmaxf(acc[t][j][1] + b1, 0.f)));
            v1.x = __uint_as_float(f2tf32(fmaxf(acc[t][j][2] + b0, 0.f)));
            v1.y = __uint_as_float(f2tf32(fmaxf(acc[t][j][3] + b1, 0.f)));
            *reinterpret_cast<float2*>(&g_hidden[(size_t)row * HID + col])       = v0;
            *reinterpret_cast<float2*>(&g_hidden[(size_t)(row + 8) * HID + col]) = v1;
        }
    }
}

// ---------------------------------------------------------------------------
// Kernel B: one CTA per N-tile; loops over all 8 M-tiles.
//   - B tile (W_heads) loaded ONCE per CTA (full K=128 in smem)
//   - A tiles double-buffered via cp.async (g_hidden stays L2-resident)
// ---------------------------------------------------------------------------
__global__ void __launch_bounds__(256)
head_gemm(const float* __restrict__ Wheads,
          const float* __restrict__ bheads,
          float* __restrict__ out)
{
    extern __shared__ float smem[];
    float* Bs = smem;                 // [128][SSTK]
    float* A0 = smem + ATILE;         // A buffers [2][128][SSTK]

    const int ntg = blockIdx.x;

    int h = 0;
    #pragma unroll
    for (int i = 1; i < NUM_HEADS; ++i) h += (ntg >= c_tile_start[i]);
    const int ntile = ntg - c_tile_start[h];
    const int p  = c_p[h];
    const int n0 = ntile * BN;

    const float* Bg   = Wheads + (size_t)h * PMAX * DSLICE;
    const float* bias = bheads + (size_t)h * PMAX;
    float* Og = out + (size_t)c_cum[h] * BROWS;
    const float* Ahead = g_hidden + (size_t)h * DSLICE;

    const int tid  = threadIdx.x;
    const int lane = tid & 31;
    const int warp = tid >> 5;
    const int wm = warp >> 1;
    const int wn = warp & 1;

    // Prefetch A tile 0 via cp.async
    #pragma unroll
    for (int it = 0; it < 16; ++it) {
        int slot = tid + it * 256;
        int r  = slot >> 5;
        int c4 = (slot & 31) * 4;
        cp_async16(A0 + r * SSTK + c4, Ahead + (size_t)r * HID + c4);
    }
    asm volatile("cp.async.commit_group;\n");

    // Load B tile once (LDG + tf32 round + STS), full K=128
    #pragma unroll
    for (int it = 0; it < 16; ++it) {
        int slot = tid + it * 256;
        int r  = slot >> 5;
        int c4 = (slot & 31) * 4;
        float4 vb;
        if (n0 + r < p) {
            vb = *reinterpret_cast<const float4*>(
                Bg + (size_t)(n0 + r) * DSLICE + c4);
        } else {
            vb = make_float4(0.f, 0.f, 0.f, 0.f);
        }
        Bs[r * SSTK + c4 + 0] = __uint_as_float(f2tf32(vb.x));
        Bs[r * SSTK + c4 + 1] = __uint_as_float(f2tf32(vb.y));
        Bs[r * SSTK + c4 + 2] = __uint_as_float(f2tf32(vb.z));
        Bs[r * SSTK + c4 + 3] = __uint_as_float(f2tf32(vb.w));
    }

    // Hoist bias loads (column layout identical for every M-tile)
    float bs0[8], bs1[8];
    #pragma unroll
    for (int j = 0; j < 8; ++j) {
        int col = n0 + wn * 64 + j * 8 + 2 * (lane & 3);
        bs0[j] = (col < p) ? bias[col]     : 0.f;
        bs1[j] = (col < p) ? bias[col + 1] : 0.f;
    }

    asm volatile("cp.async.wait_group 0;\n");
    __syncthreads();

    for (int mt = 0; mt < MTILES; ++mt) {
        // Prefetch next A tile into the other buffer
        if (mt + 1 < MTILES) {
            const float* Ag = Ahead + (size_t)((mt + 1) * BM) * HID;
            float* dst = A0 + ((mt + 1) & 1) * ATILE;
            #pragma unroll
            for (int it = 0; it < 16; ++it) {
                int slot = tid + it * 256;
                int r  = slot >> 5;
                int c4 = (slot & 31) * 4;
                cp_async16(dst + r * SSTK + c4, Ag + (size_t)r * HID + c4);
            }
            asm volatile("cp.async.commit_group;\n");
        }

        const float* Ab = A0 + (mt & 1) * ATILE;

        float acc[2][8][4];
        #pragma unroll
        for (int t = 0; t < 2; ++t)
            #pragma unroll
            for (int j = 0; j < 8; ++j)
                #pragma unroll
                for (int q = 0; q < 4; ++q) acc[t][j][q] = 0.f;

        #pragma unroll
        for (int ks = 0; ks < DSLICE; ks += 8) {
            uint32_t a[2][4];
            #pragma unroll
            for (int t = 0; t < 2; ++t) {
                int row = wm * 32 + t * 16 + (lane >> 2);
                int kc  = ks + (lane & 3);
                a[t][0] = __float_as_uint(Ab[row * SSTK + kc]);
                a[t][1] = __float_as_uint(Ab[(row + 8) * SSTK + kc]);
                a[t][2] = __float_as_uint(Ab[row * SSTK + kc + 4]);
                a[t][3] = __float_as_uint(Ab[(row + 8) * SSTK + kc + 4]);
            }
            #pragma unroll
            for (int j = 0; j < 8; ++j) {
                int col = wn * 64 + j * 8 + (lane >> 2);
                int kc  = ks + (lane & 3);
                uint32_t b[2];
                b[0] = __float_as_uint(Bs[col * SSTK + kc]);
                b[1] = __float_as_uint(Bs[col * SSTK + kc + 4]);
                mma_tf32(acc[0][j], a[0], b);
                mma_tf32(acc[1][j], a[1], b);
            }
        }

        // Epilogue for this M-tile
        const int m0 = mt * BM;
        #pragma unroll
        for (int t = 0; t < 2; ++t) {
            int row = m0 + wm * 32 + t * 16 + (lane >> 2);
            #pragma unroll
            for (int j = 0; j < 8; ++j) {
                int col = n0 + wn * 64 + j * 8 + 2 * (lane & 3);
                if (col < p) {
                    float2 v0 = make_float2(acc[t][j][0] + bs0[j], acc[t][j][1] + bs1[j]);
                    float2 v1 = make_float2(acc[t][j][2] + bs0[j], acc[t][j][3] + bs1[j]);
                    *reinterpret_cast<float2*>(&Og[(size_t)row * p + col])       = v0;
                    *reinterpret_cast<float2*>(&Og[(size_t)(row + 8) * p + col]) = v1;
                }
            }
        }

        asm volatile("cp.async.wait_group 0;\n");
        __syncthreads();
    }
}

} // anonymous namespace

extern "C" void kernel_launch(void* const* d_in, const int* in_sizes, int n_in,
                              void* d_out, int out_size) {
    (void)in_sizes; (void)n_in; (void)out_size;
    const float* x      = (const float*)d_in[0];
    const float* Wh     = (const float*)d_in[1];
    const float* bh     = (const float*)d_in[2];
    const float* Wheads = (const float*)d_in[3];
    const float* bheads = (const float*)d_in[4];
    float* out = (float*)d_out;

    static bool attr_set = false;
    if (!attr_set) {
        cudaFuncSetAttribute(head_gemm,
                             cudaFuncAttributeMaxDynamicSharedMemorySize,
                             (int)HEAD_SMEM_BYTES);
        attr_set = true;
    }

    hidden_gemm<<<MTILES * (HID / BN), 256>>>(x, Wh, bh);
    head_gemm<<<TOTAL_NTILES, 256, HEAD_SMEM_BYTES>>>(Wheads, bheads, out);
}